// round 14
// baseline (speedup 1.0000x reference)
#include <cuda_runtime.h>
#include <cuda_fp16.h>
#include <math.h>
#include <stdint.h>

#define NPTS 8192
#define NSRC 4096
#define DIM  256
#define TILE 128
#define NT   (NPTS / TILE)          // 64
#define NBLK (NT * (NT + 1) / 2)    // 2080 upper-triangle tile pairs

// ---------------------------------------------------------------- scratch
// Device globals are zero-initialized at module load; the LAST main-kernel
// CTA re-zeros all accumulators each run so graph replays start clean.
__device__ float        g_sq[NPTS];
__device__ double       g_colsum[DIM];
__device__ double       g_sumsq;
__device__ double       g_acc;
__device__ unsigned int g_done;
__device__ __half       g_h[NPTS * DIM];

// ---------------------------------------------------------------- helpers
__device__ __forceinline__ uint32_t smem_u32(const void* p) {
    uint32_t a;
    asm("{ .reg .u64 t; cvta.to.shared.u64 t, %1; cvt.u32.u64 %0, t; }" : "=r"(a) : "l"(p));
    return a;
}
#define CP_ASYNC16(dst, src) \
    asm volatile("cp.async.cg.shared.global [%0], [%1], 16;" :: "r"(dst), "l"(src))
#define CP_COMMIT() asm volatile("cp.async.commit_group;" ::: "memory")
#define CP_WAIT1()  asm volatile("cp.async.wait_group 1;" ::: "memory")

#define LDSM_X4(r0, r1, r2, r3, a) \
    asm volatile("ldmatrix.sync.aligned.m8n8.x4.shared.b16 {%0,%1,%2,%3}, [%4];" \
        : "=r"(r0), "=r"(r1), "=r"(r2), "=r"(r3) : "r"(a))

// fp16-accumulator MMA: D,C packed 2 halves/reg
#define MMA_F16A(d, a, b0, b1) \
    asm volatile("mma.sync.aligned.m16n8k16.row.col.f16.f16.f16.f16 " \
        "{%0,%1}, {%2,%3,%4,%5}, {%6,%7}, {%0,%1};" \
        : "+r"((d)[0]), "+r"((d)[1]) \
        : "r"((a)[0]), "r"((a)[1]), "r"((a)[2]), "r"((a)[3]), "r"(b0), "r"(b1))

#define EX2F(u, t) asm("ex2.approx.ftz.f32 %0, %1;" : "=f"(u) : "f"(t))

__device__ __forceinline__ const float* row_ptr(const float* src, const float* tgt, int i) {
    return (i < NSRC) ? (src + (size_t)i * DIM) : (tgt + (size_t)(i - NSRC) * DIM);
}

// ---------------------------------------------------------------- prep kernel
// 256 blocks x 256 threads; block handles 32 rows (warp -> 4 rows).
// Fused: fp16 convert + per-row ||x||^2 + column sums.
__global__ void prep_kernel(const float* __restrict__ src, const float* __restrict__ tgt) {
    __shared__ float cs[DIM];
    int tid  = threadIdx.x;
    int wid  = tid >> 5;
    int lane = tid & 31;
    cs[tid] = 0.f;
    __syncthreads();

    float col_acc[8] = {0, 0, 0, 0, 0, 0, 0, 0};
    float sq_acc = 0.f;

    int rbase = blockIdx.x * 32 + wid * 4;
    for (int rr = 0; rr < 4; rr++) {
        int row = rbase + rr;
        const float4* p4 = (const float4*)row_ptr(src, tgt, row);
        float s = 0.f;
#pragma unroll
        for (int t = 0; t < 2; t++) {
            float4 v = p4[lane + t * 32];
            float x[4] = {v.x, v.y, v.z, v.w};
            uint32_t hb[4];
#pragma unroll
            for (int k = 0; k < 4; k++) {
                s += x[k] * x[k];
                col_acc[t * 4 + k] += x[k];
                hb[k] = (uint32_t)__half_as_ushort(__float2half_rn(x[k]));
            }
            size_t q = (size_t)row * 64 + lane + t * 32;   // uint2 index (4 halves)
            ((uint2*)g_h)[q] = make_uint2(hb[0] | (hb[1] << 16), hb[2] | (hb[3] << 16));
        }
#pragma unroll
        for (int o = 16; o > 0; o >>= 1) s += __shfl_xor_sync(0xffffffffu, s, o);
        if (lane == 0) { g_sq[row] = s; sq_acc += s; }
    }
    if (lane == 0) atomicAdd(&g_sumsq, (double)sq_acc);

#pragma unroll
    for (int t = 0; t < 2; t++)
#pragma unroll
        for (int k = 0; k < 4; k++)
            atomicAdd(&cs[t * 128 + lane * 4 + k], col_acc[t * 4 + k]);
    __syncthreads();
    atomicAdd(&g_colsum[tid], (double)cs[tid]);
}

// ---------------------------------------------------------------- main tile kernel
// 256 threads, 8 warps (2x4), warp tile 64x32, CTA tile 128x128; 2 CTAs/SM.
// K chunk = 64: smem arrays per stage: A, B; each 128 rows x 144B (64 fp16 + 16 pad)
#define STRIDE_B    144
#define ARR_BYTES   (128 * STRIDE_B)        // 18432
#define STAGE_BYTES (2 * ARR_BYTES)         // 36864
#define NSTAGE      3
#define NCHUNK      4
#define DYN_SMEM    (NSTAGE * STAGE_BYTES)  // 110592

__global__ void __launch_bounds__(256, 2)
mmd_mma_kernel(float* __restrict__ out) {
    extern __shared__ char dsmem[];
    __shared__ float  red[8];
    __shared__ double dred[8];
    __shared__ float  s_cexp;
    __shared__ int    s_last;
    __shared__ float  sqa_s[TILE];
    __shared__ float  sqb_s[TILE];

    uint32_t dyn_u = smem_u32(dsmem);
    int tid  = threadIdx.x;
    int wid  = tid >> 5;
    int lane = tid & 31;
    int wm   = wid & 1;       // 2 warp-rows of 64
    int wn   = wid >> 1;      // 4 warp-cols of 32

    // decode linear block id -> (bi, bj), bi <= bj
    int b = blockIdx.x;
    float fb = (float)b;
    int bi = (int)((2.0f * NT + 1.0f - sqrtf((2.0f * NT + 1.0f) * (2.0f * NT + 1.0f) - 8.0f * fb)) * 0.5f);
    if (bi < 0) bi = 0;
    if (bi >= NT) bi = NT - 1;
#define TRI_START(i) ((i) * NT - (i) * ((i) - 1) / 2)
    while (bi + 1 < NT && TRI_START(bi + 1) <= b) bi++;
    while (bi > 0 && TRI_START(bi) > b) bi--;
    int bj = bi + (b - TRI_START(bi));
#undef TRI_START
    int row0 = bi * TILE;
    int col0 = bj * TILE;

    const char* gbase[2];
    gbase[0] = (const char*)(g_h + (size_t)row0 * DIM);   // A
    gbase[1] = (const char*)(g_h + (size_t)col0 * DIM);   // B

    // loader: chunk c = k bytes [c*128, c*128+128); 2048 x 16B; 256 threads -> 8 each
#define ISSUE_LOADS(c, s) do { \
    _Pragma("unroll") \
    for (int i = 0; i < 8; i++) { \
        int arr = i >> 2; \
        int rem = tid + (i & 3) * 256;      /* 0..1023 */ \
        int row = rem >> 3; \
        int q   = rem & 7; \
        const char* srcp = gbase[arr] + (size_t)row * 512 + (c) * 128 + q * 16; \
        uint32_t dst = dyn_u + (s) * STAGE_BYTES + arr * ARR_BYTES + row * STRIDE_B + q * 16; \
        CP_ASYNC16(dst, srcp); \
    } \
    CP_COMMIT(); \
} while (0)

    ISSUE_LOADS(0, 0);
    ISSUE_LOADS(1, 1);

    // ---- per-CTA bandwidth constant (replaces finalize kernel) ----
    {
        double cv = g_colsum[tid];           // blockDim == DIM == 256
        cv = cv * cv;
#pragma unroll
        for (int o = 16; o > 0; o >>= 1) cv += __shfl_xor_sync(0xffffffffu, cv, o);
        if (lane == 0) dred[wid] = cv;
        if (tid < TILE) {
            sqa_s[tid] = g_sq[row0 + tid];
            sqb_s[tid] = g_sq[col0 + tid];
        }
        __syncthreads();
        if (tid == 0) {
            double sc = 0.0;
#pragma unroll
            for (int i = 0; i < 8; i++) sc += dred[i];
            double n = (double)NPTS;
            double sumL2 = 2.0 * n * g_sumsq - 2.0 * sc;
            double bw = sumL2 / (n * n - n) / 4.0;   // / KERNEL_MUL^(KERNEL_NUM//2)
            s_cexp = (float)(-1.0 / (16.0 * bw * 0.6931471805599453));
        }
        __syncthreads();
    }

    uint32_t acc[4][4][2];    // fp16x2 accumulators
#pragma unroll
    for (int mi = 0; mi < 4; mi++)
#pragma unroll
        for (int ni = 0; ni < 4; ni++) {
            acc[mi][ni][0] = 0u;
            acc[mi][ni][1] = 0u;
        }

    // ldmatrix lane-address components
    int a_m    = lane >> 3;
    int a_rofs = ((a_m & 1) << 3) + (lane & 7);
    int a_koff = (a_m >> 1) << 4;
    int b_nofs = ((a_m >> 1) << 3) + (lane & 7);
    int b_koff = (a_m & 1) << 4;

    // fragment loader (double-buffered)
#define LOAD_FRAGS(buf, stage_u, ks) do { \
    _Pragma("unroll") \
    for (int mi = 0; mi < 4; mi++) { \
        int r = wm * 64 + mi * 16 + a_rofs; \
        uint32_t ad = (stage_u) + r * STRIDE_B + (ks) * 32 + a_koff; \
        LDSM_X4(Af[buf][mi][0], Af[buf][mi][1], Af[buf][mi][2], Af[buf][mi][3], ad); \
    } \
    _Pragma("unroll") \
    for (int pi = 0; pi < 2; pi++) { \
        int nl = wn * 32 + pi * 16 + b_nofs; \
        uint32_t bd = (stage_u) + ARR_BYTES + nl * STRIDE_B + (ks) * 32 + b_koff; \
        LDSM_X4(Bf[buf][pi][0], Bf[buf][pi][1], Bf[buf][pi][2], Bf[buf][pi][3], bd); \
    } \
} while (0)

#define DO_MMAS(buf) do { \
    _Pragma("unroll") \
    for (int mi = 0; mi < 4; mi++) { \
        _Pragma("unroll") \
        for (int ni = 0; ni < 4; ni++) { \
            int pi = ni >> 1, h = (ni & 1) * 2; \
            MMA_F16A(acc[mi][ni], Af[buf][mi], Bf[buf][pi][h], Bf[buf][pi][h + 1]); \
        } \
    } \
} while (0)

    uint32_t Af[2][4][4], Bf[2][2][4];

    for (int c = 0; c < NCHUNK; c++) {
        CP_WAIT1();           // chunk c resident
        __syncthreads();      // all warps past chunk c-1 compute; stage (c+2)%3 free
        if (c + 2 < NCHUNK) ISSUE_LOADS(c + 2, (c + 2) % NSTAGE);
        else CP_COMMIT();     // empty group keeps wait_group accounting exact

        uint32_t stage_u = dyn_u + (c % NSTAGE) * STAGE_BYTES;
        LOAD_FRAGS(0, stage_u, 0);
#pragma unroll
        for (int ks = 0; ks < 4; ks++) {
            int cur = ks & 1;
            if (ks < 3) LOAD_FRAGS(cur ^ 1, stage_u, ks + 1);
            DO_MMAS(cur);
        }
        // no trailing sync: next chunk's top barrier orders reads before refill
    }

    // ---------------- epilogue (fp32 exp + fp32 accumulation) ----------------
    // element map: row = wm*64+mi*16 + lane/4 + (p)*8 ; col = wn*32+ni*8 + (lane%4)*2 + {0,1}
    float cexp = s_cexp;
    float m2c  = -2.f * cexp;
    int rlo = lane >> 2;
    int cl0 = (lane & 3) * 2;

    float tB0[4], tB1[4];
#pragma unroll
    for (int ni = 0; ni < 4; ni++) {
        tB0[ni] = cexp * sqb_s[wn * 32 + ni * 8 + cl0];
        tB1[ni] = cexp * sqb_s[wn * 32 + ni * 8 + cl0 + 1];
    }

    float s = 0.f;
#pragma unroll
    for (int mi = 0; mi < 4; mi++) {
        float tA[2];
        tA[0] = cexp * sqa_s[wm * 64 + mi * 16 + rlo];
        tA[1] = cexp * sqa_s[wm * 64 + mi * 16 + rlo + 8];
#pragma unroll
        for (int ni = 0; ni < 4; ni++) {
#pragma unroll
            for (int p = 0; p < 2; p++) {
                float2 d = __half22float2(*(__half2*)&acc[mi][ni][p]);
                float t0 = fmaf(d.x, m2c, tA[p] + tB0[ni]);
                float t1 = fmaf(d.y, m2c, tA[p] + tB1[ni]);
                float u0, u1;
                EX2F(u0, t0);
                EX2F(u1, t1);
                __half2 u   = __floats2half2_rn(u0, u1);   // u in [0,1]
                __half2 u2  = __hmul2(u, u);
                __half2 u4  = __hmul2(u2, u2);
                __half2 u8  = __hmul2(u4, u4);
                __half2 u16 = __hmul2(u8, u8);
                __half2 sm  = __hadd2(__hadd2(__hadd2(u, u2), __hadd2(u4, u8)), u16);
                float2 f = __half22float2(sm);             // fp32 accumulate: no truncation bias
                s += f.x + f.y;
            }
        }
    }

    // warp-shuffle reduce, then tiny cross-warp fold
#pragma unroll
    for (int o = 16; o > 0; o >>= 1) s += __shfl_xor_sync(0xffffffffu, s, o);
    if (lane == 0) red[wid] = s;
    __syncthreads();
    if (tid == 0) {
        float t = 0.f;
#pragma unroll
        for (int i = 0; i < 8; i++) t += red[i];
        float w  = (bi == bj) ? 1.f : 2.f;
        float sr = (row0 < NSRC) ? 1.f : -1.f;
        float sc = (col0 < NSRC) ? 1.f : -1.f;
        atomicAdd(&g_acc, (double)(t * w * sr * sc));
        __threadfence();
        unsigned old = atomicAdd(&g_done, 1u);
        s_last = (old == NBLK - 1) ? 1 : 0;
    }
    __syncthreads();

    // Last CTA: write output and reset all accumulators for the next replay.
    if (s_last) {
        if (tid == 0) {
            double a = *((volatile double*)&g_acc);
            out[0] = (float)(a / ((double)NSRC * (double)NSRC));
            g_acc = 0.0;
            g_sumsq = 0.0;
            g_done = 0u;
        }
        g_colsum[tid] = 0.0;
    }
}

// ---------------------------------------------------------------- launch
extern "C" void kernel_launch(void* const* d_in, const int* in_sizes, int n_in,
                              void* d_out, int out_size) {
    const float* src = (const float*)d_in[0];
    const float* tgt = (const float*)d_in[1];
    float* out = (float*)d_out;

    cudaFuncSetAttribute(mmd_mma_kernel, cudaFuncAttributeMaxDynamicSharedMemorySize, DYN_SMEM);

    prep_kernel<<<NPTS / 32, 256>>>(src, tgt);     // fp16 convert + norms + colsums fused
    mmd_mma_kernel<<<NBLK, 256, DYN_SMEM>>>(out);
}

// round 15
// speedup vs baseline: 1.0257x; 1.0257x over previous
#include <cuda_runtime.h>
#include <cuda_fp16.h>
#include <math.h>
#include <stdint.h>

#define NPTS 8192
#define NSRC 4096
#define DIM  256
#define TILE 128
#define NT   (NPTS / TILE)          // 64
#define NBLK (NT * (NT + 1) / 2)    // 2080 upper-triangle tile pairs

// ---------------------------------------------------------------- scratch
// Device globals are zero-initialized at module load; the LAST main-kernel
// CTA re-zeros all accumulators each run so graph replays start clean.
__device__ float        g_sq[NPTS];
__device__ double       g_colsum[DIM];
__device__ double       g_sumsq;
__device__ double       g_acc;
__device__ unsigned int g_done;
__device__ __half       g_h[NPTS * DIM];

// ---------------------------------------------------------------- helpers
__device__ __forceinline__ uint32_t smem_u32(const void* p) {
    uint32_t a;
    asm("{ .reg .u64 t; cvta.to.shared.u64 t, %1; cvt.u32.u64 %0, t; }" : "=r"(a) : "l"(p));
    return a;
}
#define CP_ASYNC16(dst, src) \
    asm volatile("cp.async.cg.shared.global [%0], [%1], 16;" :: "r"(dst), "l"(src))
#define CP_COMMIT() asm volatile("cp.async.commit_group;" ::: "memory")
#define CP_WAIT1()  asm volatile("cp.async.wait_group 1;" ::: "memory")

#define LDSM_X4(r0, r1, r2, r3, a) \
    asm volatile("ldmatrix.sync.aligned.m8n8.x4.shared.b16 {%0,%1,%2,%3}, [%4];" \
        : "=r"(r0), "=r"(r1), "=r"(r2), "=r"(r3) : "r"(a))

// fp16-accumulator MMA: D,C packed 2 halves/reg
#define MMA_F16A(d, a, b0, b1) \
    asm volatile("mma.sync.aligned.m16n8k16.row.col.f16.f16.f16.f16 " \
        "{%0,%1}, {%2,%3,%4,%5}, {%6,%7}, {%0,%1};" \
        : "+r"((d)[0]), "+r"((d)[1]) \
        : "r"((a)[0]), "r"((a)[1]), "r"((a)[2]), "r"((a)[3]), "r"(b0), "r"(b1))

#define EX2F(u, t) asm("ex2.approx.ftz.f32 %0, %1;" : "=f"(u) : "f"(t))

// packed f32x2 ops (sm_100+ base ISA)
#define PACK2(o, lo, hi) asm("mov.b64 %0, {%1, %2};" : "=l"(o) : "f"(lo), "f"(hi))
#define UNPACK2(lo, hi, v) asm("mov.b64 {%0, %1}, %2;" : "=f"(lo), "=f"(hi) : "l"(v))
#define MUL2(o, a, b) asm("mul.rn.f32x2 %0, %1, %2;" : "=l"(o) : "l"(a), "l"(b))
#define ADD2(o, a, b) asm("add.rn.f32x2 %0, %1, %2;" : "=l"(o) : "l"(a), "l"(b))
#define FMA2(o, a, b, c) asm("fma.rn.f32x2 %0, %1, %2, %3;" : "=l"(o) : "l"(a), "l"(b), "l"(c))

__device__ __forceinline__ const float* row_ptr(const float* src, const float* tgt, int i) {
    return (i < NSRC) ? (src + (size_t)i * DIM) : (tgt + (size_t)(i - NSRC) * DIM);
}

// ---------------------------------------------------------------- prep kernel
// 256 blocks x 256 threads; block handles 32 rows (warp -> 4 rows).
// Fused: fp16 convert + per-row ||x||^2 + column sums.
__global__ void prep_kernel(const float* __restrict__ src, const float* __restrict__ tgt) {
    __shared__ float cs[DIM];
    int tid  = threadIdx.x;
    int wid  = tid >> 5;
    int lane = tid & 31;
    cs[tid] = 0.f;
    __syncthreads();

    float col_acc[8] = {0, 0, 0, 0, 0, 0, 0, 0};
    float sq_acc = 0.f;

    int rbase = blockIdx.x * 32 + wid * 4;
    for (int rr = 0; rr < 4; rr++) {
        int row = rbase + rr;
        const float4* p4 = (const float4*)row_ptr(src, tgt, row);
        float s = 0.f;
#pragma unroll
        for (int t = 0; t < 2; t++) {
            float4 v = p4[lane + t * 32];
            float x[4] = {v.x, v.y, v.z, v.w};
            uint32_t hb[4];
#pragma unroll
            for (int k = 0; k < 4; k++) {
                s += x[k] * x[k];
                col_acc[t * 4 + k] += x[k];
                hb[k] = (uint32_t)__half_as_ushort(__float2half_rn(x[k]));
            }
            size_t q = (size_t)row * 64 + lane + t * 32;   // uint2 index (4 halves)
            ((uint2*)g_h)[q] = make_uint2(hb[0] | (hb[1] << 16), hb[2] | (hb[3] << 16));
        }
#pragma unroll
        for (int o = 16; o > 0; o >>= 1) s += __shfl_xor_sync(0xffffffffu, s, o);
        if (lane == 0) { g_sq[row] = s; sq_acc += s; }
    }
    if (lane == 0) atomicAdd(&g_sumsq, (double)sq_acc);

#pragma unroll
    for (int t = 0; t < 2; t++)
#pragma unroll
        for (int k = 0; k < 4; k++)
            atomicAdd(&cs[t * 128 + lane * 4 + k], col_acc[t * 4 + k]);
    __syncthreads();
    atomicAdd(&g_colsum[tid], (double)cs[tid]);
}

// ---------------------------------------------------------------- main tile kernel
// 256 threads, 8 warps (2x4), warp tile 64x32, CTA tile 128x128; 2 CTAs/SM.
// K chunk = 64: smem arrays per stage: A, B; each 128 rows x 144B (64 fp16 + 16 pad)
#define STRIDE_B    144
#define ARR_BYTES   (128 * STRIDE_B)        // 18432
#define STAGE_BYTES (2 * ARR_BYTES)         // 36864
#define NSTAGE      3
#define NCHUNK      4
#define DYN_SMEM    (NSTAGE * STAGE_BYTES)  // 110592

__global__ void __launch_bounds__(256, 2)
mmd_mma_kernel(float* __restrict__ out) {
    extern __shared__ char dsmem[];
    __shared__ float  red[8];
    __shared__ float  s_cexp;
    __shared__ int    s_last;
    __shared__ float  sqa_s[TILE];
    __shared__ float  sqb_s[TILE];

    uint32_t dyn_u = smem_u32(dsmem);
    int tid  = threadIdx.x;
    int wid  = tid >> 5;
    int lane = tid & 31;
    int wm   = wid & 1;       // 2 warp-rows of 64
    int wn   = wid >> 1;      // 4 warp-cols of 32

    // decode linear block id -> (bi, bj), bi <= bj
    int b = blockIdx.x;
    float fb = (float)b;
    int bi = (int)((2.0f * NT + 1.0f - sqrtf((2.0f * NT + 1.0f) * (2.0f * NT + 1.0f) - 8.0f * fb)) * 0.5f);
    if (bi < 0) bi = 0;
    if (bi >= NT) bi = NT - 1;
#define TRI_START(i) ((i) * NT - (i) * ((i) - 1) / 2)
    while (bi + 1 < NT && TRI_START(bi + 1) <= b) bi++;
    while (bi > 0 && TRI_START(bi) > b) bi--;
    int bj = bi + (b - TRI_START(bi));
#undef TRI_START
    int row0 = bi * TILE;
    int col0 = bj * TILE;

    const char* gbase[2];
    gbase[0] = (const char*)(g_h + (size_t)row0 * DIM);   // A
    gbase[1] = (const char*)(g_h + (size_t)col0 * DIM);   // B

    // loader: chunk c = k bytes [c*128, c*128+128); 2048 x 16B; 256 threads -> 8 each
#define ISSUE_LOADS(c, s) do { \
    _Pragma("unroll") \
    for (int i = 0; i < 8; i++) { \
        int arr = i >> 2; \
        int rem = tid + (i & 3) * 256;      /* 0..1023 */ \
        int row = rem >> 3; \
        int q   = rem & 7; \
        const char* srcp = gbase[arr] + (size_t)row * 512 + (c) * 128 + q * 16; \
        uint32_t dst = dyn_u + (s) * STAGE_BYTES + arr * ARR_BYTES + row * STRIDE_B + q * 16; \
        CP_ASYNC16(dst, srcp); \
    } \
    CP_COMMIT(); \
} while (0)

    ISSUE_LOADS(0, 0);
    ISSUE_LOADS(1, 1);

    if (tid < TILE) {
        sqa_s[tid] = g_sq[row0 + tid];
        sqb_s[tid] = g_sq[col0 + tid];
    }

    // ---- bandwidth constant: warp 0 only, fp32 (reference computes bw in fp32) ----
    if (wid == 0) {
        float cv = 0.f;
#pragma unroll
        for (int k = 0; k < 8; k++) {
            float c = (float)g_colsum[lane * 8 + k];
            cv = fmaf(c, c, cv);
        }
#pragma unroll
        for (int o = 16; o > 0; o >>= 1) cv += __shfl_xor_sync(0xffffffffu, cv, o);
        if (lane == 0) {
            double n = (double)NPTS;
            double sumL2 = 2.0 * n * g_sumsq - 2.0 * (double)cv;
            double bw = sumL2 / (n * n - n) / 4.0;   // / KERNEL_MUL^(KERNEL_NUM//2)
            s_cexp = (float)(-1.0 / (16.0 * bw * 0.6931471805599453));
        }
    }
    // ordering of s_cexp/sqa_s/sqb_s for the epilogue is covered by the
    // chunk-loop __syncthreads barriers below.

    uint32_t acc[4][4][2];    // fp16x2 accumulators
#pragma unroll
    for (int mi = 0; mi < 4; mi++)
#pragma unroll
        for (int ni = 0; ni < 4; ni++) {
            acc[mi][ni][0] = 0u;
            acc[mi][ni][1] = 0u;
        }

    // ldmatrix lane-address components
    int a_m    = lane >> 3;
    int a_rofs = ((a_m & 1) << 3) + (lane & 7);
    int a_koff = (a_m >> 1) << 4;
    int b_nofs = ((a_m >> 1) << 3) + (lane & 7);
    int b_koff = (a_m & 1) << 4;

    // fragment loader (double-buffered)
#define LOAD_FRAGS(buf, stage_u, ks) do { \
    _Pragma("unroll") \
    for (int mi = 0; mi < 4; mi++) { \
        int r = wm * 64 + mi * 16 + a_rofs; \
        uint32_t ad = (stage_u) + r * STRIDE_B + (ks) * 32 + a_koff; \
        LDSM_X4(Af[buf][mi][0], Af[buf][mi][1], Af[buf][mi][2], Af[buf][mi][3], ad); \
    } \
    _Pragma("unroll") \
    for (int pi = 0; pi < 2; pi++) { \
        int nl = wn * 32 + pi * 16 + b_nofs; \
        uint32_t bd = (stage_u) + ARR_BYTES + nl * STRIDE_B + (ks) * 32 + b_koff; \
        LDSM_X4(Bf[buf][pi][0], Bf[buf][pi][1], Bf[buf][pi][2], Bf[buf][pi][3], bd); \
    } \
} while (0)

#define DO_MMAS(buf) do { \
    _Pragma("unroll") \
    for (int mi = 0; mi < 4; mi++) { \
        _Pragma("unroll") \
        for (int ni = 0; ni < 4; ni++) { \
            int pi = ni >> 1, h = (ni & 1) * 2; \
            MMA_F16A(acc[mi][ni], Af[buf][mi], Bf[buf][pi][h], Bf[buf][pi][h + 1]); \
        } \
    } \
} while (0)

    uint32_t Af[2][4][4], Bf[2][2][4];

    for (int c = 0; c < NCHUNK; c++) {
        CP_WAIT1();           // chunk c resident
        __syncthreads();      // all warps past chunk c-1 compute; stage (c+2)%3 free
        if (c + 2 < NCHUNK) ISSUE_LOADS(c + 2, (c + 2) % NSTAGE);
        else CP_COMMIT();     // empty group keeps wait_group accounting exact

        uint32_t stage_u = dyn_u + (c % NSTAGE) * STAGE_BYTES;
        LOAD_FRAGS(0, stage_u, 0);
#pragma unroll
        for (int ks = 0; ks < 4; ks++) {
            int cur = ks & 1;
            if (ks < 3) LOAD_FRAGS(cur ^ 1, stage_u, ks + 1);
            DO_MMAS(cur);
        }
        // no trailing sync: next chunk's top barrier orders reads before refill
    }

    // ---------------- epilogue: packed f32x2, full fp32 precision ----------------
    // element map: row = wm*64+mi*16 + lane/4 + (p)*8 ; col = wn*32+ni*8 + (lane%4)*2 + {0,1}
    float cexp = s_cexp;
    float m2c  = -2.f * cexp;
    int rlo = lane >> 2;
    int cl0 = (lane & 3) * 2;

    uint64_t M2C, tB2[4];
    PACK2(M2C, m2c, m2c);
#pragma unroll
    for (int ni = 0; ni < 4; ni++) {
        float b0 = cexp * sqb_s[wn * 32 + ni * 8 + cl0];
        float b1 = cexp * sqb_s[wn * 32 + ni * 8 + cl0 + 1];
        PACK2(tB2[ni], b0, b1);
    }

    uint64_t S2;
    PACK2(S2, 0.f, 0.f);
#pragma unroll
    for (int mi = 0; mi < 4; mi++) {
        uint64_t tA2[2];
        {
            float a0 = cexp * sqa_s[wm * 64 + mi * 16 + rlo];
            float a1 = cexp * sqa_s[wm * 64 + mi * 16 + rlo + 8];
            PACK2(tA2[0], a0, a0);
            PACK2(tA2[1], a1, a1);
        }
#pragma unroll
        for (int ni = 0; ni < 4; ni++) {
#pragma unroll
            for (int p = 0; p < 2; p++) {
                float2 d = __half22float2(*(__half2*)&acc[mi][ni][p]);
                uint64_t D, TAB, T;
                PACK2(D, d.x, d.y);
                ADD2(TAB, tA2[p], tB2[ni]);
                FMA2(T, D, M2C, TAB);          // t = sqa + sqb - 2*dot, scaled by cexp
                float t0, t1, u0, u1;
                UNPACK2(t0, t1, T);
                EX2F(u0, t0);
                EX2F(u1, t1);
                uint64_t U, U2, U4, U8, U16, A, B, C;
                PACK2(U, u0, u1);
                MUL2(U2, U, U);
                MUL2(U4, U2, U2);
                MUL2(U8, U4, U4);
                MUL2(U16, U8, U8);
                FMA2(A, U, U, U);              // u^2 + u  ... wait: u*u+u = u^2+u
                FMA2(B, U4, U4, U4);           // u^8 + u^4
                ADD2(C, A, B);
                ADD2(C, C, U16);
                ADD2(S2, S2, C);
            }
        }
    }
    float s, shi;
    UNPACK2(s, shi, S2);
    s += shi;

    // warp-shuffle reduce, then tiny cross-warp fold
#pragma unroll
    for (int o = 16; o > 0; o >>= 1) s += __shfl_xor_sync(0xffffffffu, s, o);
    if (lane == 0) red[wid] = s;
    __syncthreads();
    if (tid == 0) {
        float t = 0.f;
#pragma unroll
        for (int i = 0; i < 8; i++) t += red[i];
        float w  = (bi == bj) ? 1.f : 2.f;
        float sr = (row0 < NSRC) ? 1.f : -1.f;
        float sc = (col0 < NSRC) ? 1.f : -1.f;
        atomicAdd(&g_acc, (double)(t * w * sr * sc));
        __threadfence();
        unsigned old = atomicAdd(&g_done, 1u);
        s_last = (old == NBLK - 1) ? 1 : 0;
    }
    __syncthreads();

    // Last CTA: write output and reset all accumulators for the next replay.
    if (s_last) {
        if (tid == 0) {
            double a = *((volatile double*)&g_acc);
            out[0] = (float)(a / ((double)NSRC * (double)NSRC));
            g_acc = 0.0;
            g_sumsq = 0.0;
            g_done = 0u;
        }
        g_colsum[tid] = 0.0;
    }
}

// ---------------------------------------------------------------- launch
extern "C" void kernel_launch(void* const* d_in, const int* in_sizes, int n_in,
                              void* d_out, int out_size) {
    const float* src = (const float*)d_in[0];
    const float* tgt = (const float*)d_in[1];
    float* out = (float*)d_out;

    cudaFuncSetAttribute(mmd_mma_kernel, cudaFuncAttributeMaxDynamicSharedMemorySize, DYN_SMEM);

    prep_kernel<<<NPTS / 32, 256>>>(src, tgt);     // fp16 convert + norms + colsums fused
    mmd_mma_kernel<<<NBLK, 256, DYN_SMEM>>>(out);
}

// round 16
// speedup vs baseline: 1.0884x; 1.0611x over previous
#include <cuda_runtime.h>
#include <cuda_fp16.h>
#include <math.h>
#include <stdint.h>

#define NPTS 8192
#define NSRC 4096
#define DIM  256
#define TILE 128
#define NT   (NPTS / TILE)          // 64
#define NBLK (NT * (NT + 1) / 2)    // 2080 upper-triangle tile pairs

// ---------------------------------------------------------------- scratch
// Device globals are zero-initialized at module load; writeout_kernel
// re-zeros the accumulators each run so graph replays start clean.
__device__ float  g_sq[NPTS];
__device__ double g_colsum[DIM];
__device__ double g_sumsq;
__device__ double g_acc;
__device__ __half g_h[NPTS * DIM];

// ---------------------------------------------------------------- helpers
__device__ __forceinline__ uint32_t smem_u32(const void* p) {
    uint32_t a;
    asm("{ .reg .u64 t; cvta.to.shared.u64 t, %1; cvt.u32.u64 %0, t; }" : "=r"(a) : "l"(p));
    return a;
}
#define CP_ASYNC16(dst, src) \
    asm volatile("cp.async.cg.shared.global [%0], [%1], 16;" :: "r"(dst), "l"(src))
#define CP_COMMIT() asm volatile("cp.async.commit_group;" ::: "memory")
#define CP_WAIT1()  asm volatile("cp.async.wait_group 1;" ::: "memory")

#define LDSM_X4(r0, r1, r2, r3, a) \
    asm volatile("ldmatrix.sync.aligned.m8n8.x4.shared.b16 {%0,%1,%2,%3}, [%4];" \
        : "=r"(r0), "=r"(r1), "=r"(r2), "=r"(r3) : "r"(a))

// fp16-accumulator MMA: D,C packed 2 halves/reg
#define MMA_F16A(d, a, b0, b1) \
    asm volatile("mma.sync.aligned.m16n8k16.row.col.f16.f16.f16.f16 " \
        "{%0,%1}, {%2,%3,%4,%5}, {%6,%7}, {%0,%1};" \
        : "+r"((d)[0]), "+r"((d)[1]) \
        : "r"((a)[0]), "r"((a)[1]), "r"((a)[2]), "r"((a)[3]), "r"(b0), "r"(b1))

#define EX2F(u, t) asm("ex2.approx.ftz.f32 %0, %1;" : "=f"(u) : "f"(t))

// packed f32x2 ops (sm_100+ base ISA)
#define PACK2(o, lo, hi) asm("mov.b64 %0, {%1, %2};" : "=l"(o) : "f"(lo), "f"(hi))
#define UNPACK2(lo, hi, v) asm("mov.b64 {%0, %1}, %2;" : "=f"(lo), "=f"(hi) : "l"(v))
#define MUL2(o, a, b) asm("mul.rn.f32x2 %0, %1, %2;" : "=l"(o) : "l"(a), "l"(b))
#define ADD2(o, a, b) asm("add.rn.f32x2 %0, %1, %2;" : "=l"(o) : "l"(a), "l"(b))
#define FMA2(o, a, b, c) asm("fma.rn.f32x2 %0, %1, %2, %3;" : "=l"(o) : "l"(a), "l"(b), "l"(c))

__device__ __forceinline__ const float* row_ptr(const float* src, const float* tgt, int i) {
    return (i < NSRC) ? (src + (size_t)i * DIM) : (tgt + (size_t)(i - NSRC) * DIM);
}

// ---------------------------------------------------------------- prep kernel
// 256 blocks x 256 threads; block handles 32 rows (warp -> 4 rows).
// Fused: fp16 convert + per-row ||x||^2 + column sums.
__global__ void prep_kernel(const float* __restrict__ src, const float* __restrict__ tgt) {
    __shared__ float cs[DIM];
    int tid  = threadIdx.x;
    int wid  = tid >> 5;
    int lane = tid & 31;
    cs[tid] = 0.f;
    __syncthreads();

    float col_acc[8] = {0, 0, 0, 0, 0, 0, 0, 0};
    float sq_acc = 0.f;

    int rbase = blockIdx.x * 32 + wid * 4;
    for (int rr = 0; rr < 4; rr++) {
        int row = rbase + rr;
        const float4* p4 = (const float4*)row_ptr(src, tgt, row);
        float s = 0.f;
#pragma unroll
        for (int t = 0; t < 2; t++) {
            float4 v = p4[lane + t * 32];
            float x[4] = {v.x, v.y, v.z, v.w};
            uint32_t hb[4];
#pragma unroll
            for (int k = 0; k < 4; k++) {
                s += x[k] * x[k];
                col_acc[t * 4 + k] += x[k];
                hb[k] = (uint32_t)__half_as_ushort(__float2half_rn(x[k]));
            }
            size_t q = (size_t)row * 64 + lane + t * 32;   // uint2 index (4 halves)
            ((uint2*)g_h)[q] = make_uint2(hb[0] | (hb[1] << 16), hb[2] | (hb[3] << 16));
        }
#pragma unroll
        for (int o = 16; o > 0; o >>= 1) s += __shfl_xor_sync(0xffffffffu, s, o);
        if (lane == 0) { g_sq[row] = s; sq_acc += s; }
    }
    if (lane == 0) atomicAdd(&g_sumsq, (double)sq_acc);

#pragma unroll
    for (int t = 0; t < 2; t++)
#pragma unroll
        for (int k = 0; k < 4; k++)
            atomicAdd(&cs[t * 128 + lane * 4 + k], col_acc[t * 4 + k]);
    __syncthreads();
    atomicAdd(&g_colsum[tid], (double)cs[tid]);
}

// ---------------------------------------------------------------- main tile kernel
// 256 threads, 8 warps (2x4), warp tile 64x32, CTA tile 128x128; 2 CTAs/SM.
// K chunk = 64: smem arrays per stage: A, B; each 128 rows x 144B (64 fp16 + 16 pad)
#define STRIDE_B    144
#define ARR_BYTES   (128 * STRIDE_B)        // 18432
#define STAGE_BYTES (2 * ARR_BYTES)         // 36864
#define NSTAGE      3
#define NCHUNK      4
#define DYN_SMEM    (NSTAGE * STAGE_BYTES)  // 110592

__global__ void __launch_bounds__(256, 2)
mmd_mma_kernel() {
    extern __shared__ char dsmem[];
    __shared__ float  red[8];
    __shared__ float  s_cexp;
    __shared__ float  sqa_s[TILE];
    __shared__ float  sqb_s[TILE];

    uint32_t dyn_u = smem_u32(dsmem);
    int tid  = threadIdx.x;
    int wid  = tid >> 5;
    int lane = tid & 31;
    int wm   = wid & 1;       // 2 warp-rows of 64
    int wn   = wid >> 1;      // 4 warp-cols of 32

    // decode linear block id -> (bi, bj), bi <= bj
    int b = blockIdx.x;
    float fb = (float)b;
    int bi = (int)((2.0f * NT + 1.0f - sqrtf((2.0f * NT + 1.0f) * (2.0f * NT + 1.0f) - 8.0f * fb)) * 0.5f);
    if (bi < 0) bi = 0;
    if (bi >= NT) bi = NT - 1;
#define TRI_START(i) ((i) * NT - (i) * ((i) - 1) / 2)
    while (bi + 1 < NT && TRI_START(bi + 1) <= b) bi++;
    while (bi > 0 && TRI_START(bi) > b) bi--;
    int bj = bi + (b - TRI_START(bi));
#undef TRI_START
    int row0 = bi * TILE;
    int col0 = bj * TILE;

    const char* gbase[2];
    gbase[0] = (const char*)(g_h + (size_t)row0 * DIM);   // A
    gbase[1] = (const char*)(g_h + (size_t)col0 * DIM);   // B

    // loader: chunk c = k bytes [c*128, c*128+128); 2048 x 16B; 256 threads -> 8 each
#define ISSUE_LOADS(c, s) do { \
    _Pragma("unroll") \
    for (int i = 0; i < 8; i++) { \
        int arr = i >> 2; \
        int rem = tid + (i & 3) * 256;      /* 0..1023 */ \
        int row = rem >> 3; \
        int q   = rem & 7; \
        const char* srcp = gbase[arr] + (size_t)row * 512 + (c) * 128 + q * 16; \
        uint32_t dst = dyn_u + (s) * STAGE_BYTES + arr * ARR_BYTES + row * STRIDE_B + q * 16; \
        CP_ASYNC16(dst, srcp); \
    } \
    CP_COMMIT(); \
} while (0)

    ISSUE_LOADS(0, 0);
    ISSUE_LOADS(1, 1);

    if (tid < TILE) {
        sqa_s[tid] = g_sq[row0 + tid];
        sqb_s[tid] = g_sq[col0 + tid];
    }

    // ---- bandwidth constant: warp 0 only, fp32 (reference computes bw in fp32) ----
    if (wid == 0) {
        float cv = 0.f;
#pragma unroll
        for (int k = 0; k < 8; k++) {
            float c = (float)g_colsum[lane * 8 + k];
            cv = fmaf(c, c, cv);
        }
#pragma unroll
        for (int o = 16; o > 0; o >>= 1) cv += __shfl_xor_sync(0xffffffffu, cv, o);
        if (lane == 0) {
            double n = (double)NPTS;
            double sumL2 = 2.0 * n * g_sumsq - 2.0 * (double)cv;
            double bw = sumL2 / (n * n - n) / 4.0;   // / KERNEL_MUL^(KERNEL_NUM//2)
            s_cexp = (float)(-1.0 / (16.0 * bw * 0.6931471805599453));
        }
    }
    // s_cexp/sqa_s/sqb_s ordering for the epilogue is covered by the
    // chunk-loop __syncthreads barriers below.

    uint32_t acc[4][4][2];    // fp16x2 accumulators
#pragma unroll
    for (int mi = 0; mi < 4; mi++)
#pragma unroll
        for (int ni = 0; ni < 4; ni++) {
            acc[mi][ni][0] = 0u;
            acc[mi][ni][1] = 0u;
        }

    // ldmatrix lane-address components
    int a_m    = lane >> 3;
    int a_rofs = ((a_m & 1) << 3) + (lane & 7);
    int a_koff = (a_m >> 1) << 4;
    int b_nofs = ((a_m >> 1) << 3) + (lane & 7);
    int b_koff = (a_m & 1) << 4;

    // fragment loader (double-buffered)
#define LOAD_FRAGS(buf, stage_u, ks) do { \
    _Pragma("unroll") \
    for (int mi = 0; mi < 4; mi++) { \
        int r = wm * 64 + mi * 16 + a_rofs; \
        uint32_t ad = (stage_u) + r * STRIDE_B + (ks) * 32 + a_koff; \
        LDSM_X4(Af[buf][mi][0], Af[buf][mi][1], Af[buf][mi][2], Af[buf][mi][3], ad); \
    } \
    _Pragma("unroll") \
    for (int pi = 0; pi < 2; pi++) { \
        int nl = wn * 32 + pi * 16 + b_nofs; \
        uint32_t bd = (stage_u) + ARR_BYTES + nl * STRIDE_B + (ks) * 32 + b_koff; \
        LDSM_X4(Bf[buf][pi][0], Bf[buf][pi][1], Bf[buf][pi][2], Bf[buf][pi][3], bd); \
    } \
} while (0)

#define DO_MMAS(buf) do { \
    _Pragma("unroll") \
    for (int mi = 0; mi < 4; mi++) { \
        _Pragma("unroll") \
        for (int ni = 0; ni < 4; ni++) { \
            int pi = ni >> 1, h = (ni & 1) * 2; \
            MMA_F16A(acc[mi][ni], Af[buf][mi], Bf[buf][pi][h], Bf[buf][pi][h + 1]); \
        } \
    } \
} while (0)

    uint32_t Af[2][4][4], Bf[2][2][4];

    for (int c = 0; c < NCHUNK; c++) {
        CP_WAIT1();           // chunk c resident
        __syncthreads();      // all warps past chunk c-1 compute; stage (c+2)%3 free
        if (c + 2 < NCHUNK) ISSUE_LOADS(c + 2, (c + 2) % NSTAGE);
        else CP_COMMIT();     // empty group keeps wait_group accounting exact

        uint32_t stage_u = dyn_u + (c % NSTAGE) * STAGE_BYTES;
        LOAD_FRAGS(0, stage_u, 0);
#pragma unroll
        for (int ks = 0; ks < 4; ks++) {
            int cur = ks & 1;
            if (ks < 3) LOAD_FRAGS(cur ^ 1, stage_u, ks + 1);
            DO_MMAS(cur);
        }
        // no trailing sync: next chunk's top barrier orders reads before refill
    }

    // ---------------- epilogue: packed f32x2, full fp32 precision ----------------
    // element map: row = wm*64+mi*16 + lane/4 + (p)*8 ; col = wn*32+ni*8 + (lane%4)*2 + {0,1}
    float cexp = s_cexp;
    float m2c  = -2.f * cexp;
    int rlo = lane >> 2;
    int cl0 = (lane & 3) * 2;

    uint64_t M2C, tB2[4];
    PACK2(M2C, m2c, m2c);
#pragma unroll
    for (int ni = 0; ni < 4; ni++) {
        float b0 = cexp * sqb_s[wn * 32 + ni * 8 + cl0];
        float b1 = cexp * sqb_s[wn * 32 + ni * 8 + cl0 + 1];
        PACK2(tB2[ni], b0, b1);
    }

    uint64_t S2;
    PACK2(S2, 0.f, 0.f);
#pragma unroll
    for (int mi = 0; mi < 4; mi++) {
        uint64_t tA2[2];
        {
            float a0 = cexp * sqa_s[wm * 64 + mi * 16 + rlo];
            float a1 = cexp * sqa_s[wm * 64 + mi * 16 + rlo + 8];
            PACK2(tA2[0], a0, a0);
            PACK2(tA2[1], a1, a1);
        }
#pragma unroll
        for (int ni = 0; ni < 4; ni++) {
#pragma unroll
            for (int p = 0; p < 2; p++) {
                float2 d = __half22float2(*(__half2*)&acc[mi][ni][p]);
                uint64_t D, TAB, T;
                PACK2(D, d.x, d.y);
                ADD2(TAB, tA2[p], tB2[ni]);
                FMA2(T, D, M2C, TAB);          // t = cexp*(sqa + sqb - 2*dot)
                float t0, t1, u0, u1;
                UNPACK2(t0, t1, T);
                EX2F(u0, t0);
                EX2F(u1, t1);
                uint64_t U, U2, U4, U8, U16, A, B, C;
                PACK2(U, u0, u1);
                MUL2(U2, U, U);
                MUL2(U4, U2, U2);
                MUL2(U8, U4, U4);
                MUL2(U16, U8, U8);
                FMA2(A, U, U, U);              // u^2 + u
                FMA2(B, U4, U4, U4);           // u^8 + u^4
                ADD2(C, A, B);
                ADD2(C, C, U16);
                ADD2(S2, S2, C);
            }
        }
    }
    float s, shi;
    UNPACK2(s, shi, S2);
    s += shi;

    // warp-shuffle reduce, then tiny cross-warp fold
#pragma unroll
    for (int o = 16; o > 0; o >>= 1) s += __shfl_xor_sync(0xffffffffu, s, o);
    if (lane == 0) red[wid] = s;
    __syncthreads();
    if (tid == 0) {
        float t = 0.f;
#pragma unroll
        for (int i = 0; i < 8; i++) t += red[i];
        float w  = (bi == bj) ? 1.f : 2.f;
        float sr = (row0 < NSRC) ? 1.f : -1.f;
        float sc = (col0 < NSRC) ? 1.f : -1.f;
        atomicAdd(&g_acc, (double)(t * w * sr * sc));
    }
}

// Writes result and re-zeros accumulators so the next graph replay starts clean.
__global__ void writeout_kernel(float* out) {
    int t = threadIdx.x;
    if (t == 0) out[0] = (float)(g_acc / ((double)NSRC * (double)NSRC));
    if (t < DIM) g_colsum[t] = 0.0;
    if (t == 0) { g_sumsq = 0.0; g_acc = 0.0; }
}

// ---------------------------------------------------------------- launch
extern "C" void kernel_launch(void* const* d_in, const int* in_sizes, int n_in,
                              void* d_out, int out_size) {
    const float* src = (const float*)d_in[0];
    const float* tgt = (const float*)d_in[1];
    float* out = (float*)d_out;

    cudaFuncSetAttribute(mmd_mma_kernel, cudaFuncAttributeMaxDynamicSharedMemorySize, DYN_SMEM);

    prep_kernel<<<NPTS / 32, 256>>>(src, tgt);     // fp16 convert + norms + colsums fused
    mmd_mma_kernel<<<NBLK, 256, DYN_SMEM>>>();
    writeout_kernel<<<1, 256>>>(out);
}